// round 4
// baseline (speedup 1.0000x reference)
#include <cuda_runtime.h>
#include <math.h>

#define B_  4
#define S_  1024
#define D_  768
#define H_  12
#define HD_ 64
#define F_  3072
#define L_  12
#define V_  50257
#define T_  (B_*S_)   // 4096 tokens

// ---------------- scratch (device globals; no allocation allowed) ------------
__device__ float g_x[T_*D_];
__device__ float g_h[T_*D_];
__device__ float g_qkv[T_*3*D_];
__device__ float g_attn[T_*D_];
__device__ float g_ff[(size_t)T_*F_];
__device__ float g_scores[(size_t)B_*H_*S_*S_];   // 192 MB

// ---------------- helpers ----------------------------------------------------
__device__ __forceinline__ float gelu_f(float x) {
    float x3 = x * x * x;
    float t = tanhf(0.7978845608028654f * (x + 0.044715f * x3));
    return 0.5f * x * (1.0f + t);
}

// ---------------- embedding --------------------------------------------------
__global__ void __launch_bounds__(256) embed_kernel(
    const int* __restrict__ ids, const float* __restrict__ tok,
    const float* __restrict__ pos, float* __restrict__ x)
{
    int i = blockIdx.x * 256 + threadIdx.x;        // grid exactly covers T_*D_
    int d = i % D_;
    int t = i / D_;
    int s = t & (S_ - 1);
    x[i] = tok[(size_t)ids[t] * D_ + d] + pos[(size_t)s * D_ + d];
}

// ---------------- layernorm (one block per row, 768 = 3*256) -----------------
__global__ void __launch_bounds__(256) ln_kernel(
    const float* __restrict__ x, const float* __restrict__ g,
    const float* __restrict__ b, float* __restrict__ out)
{
    int row = blockIdx.x;
    int tid = threadIdx.x;
    const float* xr = x + (size_t)row * D_;
    float* orow = out + (size_t)row * D_;

    float v0 = xr[tid], v1 = xr[tid + 256], v2 = xr[tid + 512];

    __shared__ float red[8];
    __shared__ float s_stat;

    float s = v0 + v1 + v2;
    #pragma unroll
    for (int o = 16; o; o >>= 1) s += __shfl_xor_sync(0xffffffffu, s, o);
    if ((tid & 31) == 0) red[tid >> 5] = s;
    __syncthreads();
    if (tid == 0) {
        float t = 0.f;
        #pragma unroll
        for (int i = 0; i < 8; i++) t += red[i];
        s_stat = t * (1.0f / D_);
    }
    __syncthreads();
    float mean = s_stat;
    __syncthreads();

    float d0 = v0 - mean, d1 = v1 - mean, d2 = v2 - mean;
    float s2 = d0 * d0 + d1 * d1 + d2 * d2;
    #pragma unroll
    for (int o = 16; o; o >>= 1) s2 += __shfl_xor_sync(0xffffffffu, s2, o);
    if ((tid & 31) == 0) red[tid >> 5] = s2;
    __syncthreads();
    if (tid == 0) {
        float t = 0.f;
        #pragma unroll
        for (int i = 0; i < 8; i++) t += red[i];
        s_stat = rsqrtf(t * (1.0f / D_) + 1e-5f);
    }
    __syncthreads();
    float inv = s_stat;

    orow[tid]       = g[tid]       * (d0 * inv) + b[tid];
    orow[tid + 256] = g[tid + 256] * (d1 * inv) + b[tid + 256];
    orow[tid + 512] = g[tid + 512] * (d2 * inv) + b[tid + 512];
}

// ---------------- SGEMM C = A@B (+bias, +res, +gelu) -------------------------
// 128x128 tile, BK=8, 256 threads, 8x8 per thread.
// EPI: 0 = bias, 1 = bias + residual add, 2 = bias + gelu
template<int EPI>
__global__ void __launch_bounds__(256) gemm_nn(
    const float* __restrict__ A, const float* __restrict__ B,
    const float* __restrict__ bias, const float* __restrict__ res,
    float* __restrict__ C, int M, int N, int K)
{
    __shared__ float As[8][132];   // pad 132 -> conflict-free transposed stores
    __shared__ float Bs[8][128];

    int tid = threadIdx.x;
    int m0 = blockIdx.y * 128;
    int n0 = blockIdx.x * 128;

    int aRow = tid >> 1;
    int aK   = (tid & 1) << 2;
    int bK   = tid >> 5;
    int bN   = (tid & 31) << 2;

    int warp = tid >> 5, lane = tid & 31;
    int tm = ((warp >> 1) << 5) + ((lane >> 3) << 3);          // 0..127 step 8
    int tn = ((warp & 1) << 6) + ((lane & 7) << 2);            // + {0..3, 32..35}

    const float* Ap = A + (size_t)(m0 + aRow) * K + aK;
    const float* Bp = B + (size_t)bK * N + n0 + bN;

    float acc[8][8];
    #pragma unroll
    for (int i = 0; i < 8; i++)
        #pragma unroll
        for (int j = 0; j < 8; j++) acc[i][j] = 0.f;

    for (int k0 = 0; k0 < K; k0 += 8) {
        float4 av = *(const float4*)(Ap + k0);
        float4 bv = *(const float4*)(Bp + (size_t)k0 * N);
        As[aK + 0][aRow] = av.x; As[aK + 1][aRow] = av.y;
        As[aK + 2][aRow] = av.z; As[aK + 3][aRow] = av.w;
        *(float4*)&Bs[bK][bN] = bv;
        __syncthreads();
        #pragma unroll
        for (int kk = 0; kk < 8; kk++) {
            float4 a0 = *(const float4*)&As[kk][tm];
            float4 a1 = *(const float4*)&As[kk][tm + 4];
            float4 b0 = *(const float4*)&Bs[kk][tn];
            float4 b1 = *(const float4*)&Bs[kk][tn + 32];
            float a[8] = {a0.x,a0.y,a0.z,a0.w,a1.x,a1.y,a1.z,a1.w};
            float bb2[8] = {b0.x,b0.y,b0.z,b0.w,b1.x,b1.y,b1.z,b1.w};
            #pragma unroll
            for (int i = 0; i < 8; i++)
                #pragma unroll
                for (int j = 0; j < 8; j++)
                    acc[i][j] = fmaf(a[i], bb2[j], acc[i][j]);
        }
        __syncthreads();
    }

    float bb[8];
    #pragma unroll
    for (int j = 0; j < 4; j++) {
        bb[j]     = bias[n0 + tn + j];
        bb[j + 4] = bias[n0 + tn + 32 + j];
    }

    #pragma unroll
    for (int i = 0; i < 8; i++) {
        size_t off = (size_t)(m0 + tm + i) * N + n0;
        float o[8];
        #pragma unroll
        for (int j = 0; j < 8; j++) o[j] = acc[i][j] + bb[j];
        if (EPI == 2) {
            #pragma unroll
            for (int j = 0; j < 8; j++) o[j] = gelu_f(o[j]);
        }
        if (EPI == 1) {
            float4 r0 = *(const float4*)(res + off + tn);
            float4 r1 = *(const float4*)(res + off + tn + 32);
            o[0] += r0.x; o[1] += r0.y; o[2] += r0.z; o[3] += r0.w;
            o[4] += r1.x; o[5] += r1.y; o[6] += r1.z; o[7] += r1.w;
        }
        *(float4*)(C + off + tn)      = make_float4(o[0], o[1], o[2], o[3]);
        *(float4*)(C + off + tn + 32) = make_float4(o[4], o[5], o[6], o[7]);
    }
}

// ---------------- SGEMM C = A@B^T (lm_head, Bt is [N,K], N not /128) ---------
__global__ void __launch_bounds__(256) gemm_nt(
    const float* __restrict__ A, const float* __restrict__ Bt,
    float* __restrict__ C, int M, int N, int K)
{
    __shared__ float As[8][132];
    __shared__ float Bs[8][132];

    int tid = threadIdx.x;
    int m0 = blockIdx.y * 128;
    int n0 = blockIdx.x * 128;

    int aRow = tid >> 1;
    int aK   = (tid & 1) << 2;
    int bRow = tid >> 1;                  // n within tile
    int bK   = (tid & 1) << 2;

    int warp = tid >> 5, lane = tid & 31;
    int tm = ((warp >> 1) << 5) + ((lane >> 3) << 3);
    int tn = ((warp & 1) << 6) + ((lane & 7) << 2);

    const float* Ap = A + (size_t)(m0 + aRow) * K + aK;
    bool bval = (n0 + bRow) < N;
    const float* Bp = Bt + (size_t)(n0 + bRow) * K + bK;

    float acc[8][8];
    #pragma unroll
    for (int i = 0; i < 8; i++)
        #pragma unroll
        for (int j = 0; j < 8; j++) acc[i][j] = 0.f;

    for (int k0 = 0; k0 < K; k0 += 8) {
        float4 av = *(const float4*)(Ap + k0);
        float4 bv = bval ? *(const float4*)(Bp + k0) : make_float4(0.f,0.f,0.f,0.f);
        As[aK + 0][aRow] = av.x; As[aK + 1][aRow] = av.y;
        As[aK + 2][aRow] = av.z; As[aK + 3][aRow] = av.w;
        Bs[bK + 0][bRow] = bv.x; Bs[bK + 1][bRow] = bv.y;
        Bs[bK + 2][bRow] = bv.z; Bs[bK + 3][bRow] = bv.w;
        __syncthreads();
        #pragma unroll
        for (int kk = 0; kk < 8; kk++) {
            float4 a0 = *(const float4*)&As[kk][tm];
            float4 a1 = *(const float4*)&As[kk][tm + 4];
            float4 b0 = *(const float4*)&Bs[kk][tn];
            float4 b1 = *(const float4*)&Bs[kk][tn + 32];
            float a[8] = {a0.x,a0.y,a0.z,a0.w,a1.x,a1.y,a1.z,a1.w};
            float bb2[8] = {b0.x,b0.y,b0.z,b0.w,b1.x,b1.y,b1.z,b1.w};
            #pragma unroll
            for (int i = 0; i < 8; i++)
                #pragma unroll
                for (int j = 0; j < 8; j++)
                    acc[i][j] = fmaf(a[i], bb2[j], acc[i][j]);
        }
        __syncthreads();
    }

    #pragma unroll
    for (int i = 0; i < 8; i++) {
        size_t base = (size_t)(m0 + tm + i) * N;
        #pragma unroll
        for (int j = 0; j < 4; j++) {
            int n = n0 + tn + j;
            if (n < N) C[base + n] = acc[i][j];
            int n2 = n0 + tn + 32 + j;
            if (n2 < N) C[base + n2] = acc[i][j + 4];
        }
    }
}

// ---------------- attention scores: S = scale * Q K^T (causal tiles only) ----
__global__ void __launch_bounds__(256) scores_kernel(
    const float* __restrict__ qkv, float* __restrict__ scores)
{
    int qt = blockIdx.y, kt = blockIdx.x;
    if (kt > qt) return;                     // causal: untouched region never read
    int bh = blockIdx.z;
    int b = bh / H_, h = bh - b * H_;

    __shared__ float sQ[HD_][68];
    __shared__ float sK[HD_][68];

    int tid = threadIdx.x;
    const float* Qb = qkv + ((size_t)(b * S_ + qt * 64)) * (3 * D_) + h * HD_;
    const float* Kb = qkv + ((size_t)(b * S_ + kt * 64)) * (3 * D_) + D_ + h * HD_;

    #pragma unroll
    for (int i = 0; i < 4; i++) {
        int f = tid + i * 256;               // float4 index, 0..1023
        int r = f >> 4;                      // 0..63 rows
        int d4 = (f & 15) << 2;
        float4 qv = *(const float4*)(Qb + (size_t)r * (3 * D_) + d4);
        float4 kv = *(const float4*)(Kb + (size_t)r * (3 * D_) + d4);
        sQ[d4 + 0][r] = qv.x; sQ[d4 + 1][r] = qv.y; sQ[d4 + 2][r] = qv.z; sQ[d4 + 3][r] = qv.w;
        sK[d4 + 0][r] = kv.x; sK[d4 + 1][r] = kv.y; sK[d4 + 2][r] = kv.z; sK[d4 + 3][r] = kv.w;
    }
    __syncthreads();

    int warp = tid >> 5, lane = tid & 31;
    int qi = ((warp >> 1) << 4) + ((lane >> 3) << 2);
    int ki = ((warp & 1) << 5) + ((lane & 7) << 2);

    float acc[4][4] = {};
    #pragma unroll
    for (int d = 0; d < HD_; d++) {
        float4 qa = *(const float4*)&sQ[d][qi];
        float4 kb = *(const float4*)&sK[d][ki];
        float a[4] = {qa.x, qa.y, qa.z, qa.w};
        float c[4] = {kb.x, kb.y, kb.z, kb.w};
        #pragma unroll
        for (int i = 0; i < 4; i++)
            #pragma unroll
            for (int j = 0; j < 4; j++)
                acc[i][j] = fmaf(a[i], c[j], acc[i][j]);
    }

    const float scale = 0.125f;              // 1/sqrt(64)
    float* out = scores + (size_t)bh * S_ * S_ + (size_t)(qt * 64) * S_ + kt * 64;
    #pragma unroll
    for (int i = 0; i < 4; i++) {
        *(float4*)(out + (size_t)(qi + i) * S_ + ki) =
            make_float4(acc[i][0] * scale, acc[i][1] * scale,
                        acc[i][2] * scale, acc[i][3] * scale);
    }
}

// ---------------- causal softmax over valid prefix, zero the tail ------------
__global__ void __launch_bounds__(256) softmax_kernel(float* __restrict__ scores)
{
    int r = blockIdx.x;                      // bh*S + q
    int q = r & (S_ - 1);
    float* row = scores + (size_t)r * S_;
    int n = q + 1;
    int tid = threadIdx.x;

    __shared__ float red[8];
    __shared__ float s_v;

    float mx = -1e30f;
    for (int i = tid; i < n; i += 256) mx = fmaxf(mx, row[i]);
    #pragma unroll
    for (int o = 16; o; o >>= 1) mx = fmaxf(mx, __shfl_xor_sync(0xffffffffu, mx, o));
    if ((tid & 31) == 0) red[tid >> 5] = mx;
    __syncthreads();
    if (tid == 0) {
        float t = red[0];
        #pragma unroll
        for (int i = 1; i < 8; i++) t = fmaxf(t, red[i]);
        s_v = t;
    }
    __syncthreads();
    mx = s_v;
    __syncthreads();

    float e[4];
    float sum = 0.f;
    int cnt = 0;
    for (int i = tid; i < n; i += 256) { float ev = __expf(row[i] - mx); e[cnt++] = ev; sum += ev; }
    #pragma unroll
    for (int o = 16; o; o >>= 1) sum += __shfl_xor_sync(0xffffffffu, sum, o);
    if ((tid & 31) == 0) red[tid >> 5] = sum;
    __syncthreads();
    if (tid == 0) {
        float t = 0.f;
        #pragma unroll
        for (int i = 0; i < 8; i++) t += red[i];
        s_v = 1.0f / t;
    }
    __syncthreads();
    float inv = s_v;

    cnt = 0;
    for (int i = tid; i < n; i += 256) row[i] = e[cnt++] * inv;
    for (int i = n + tid; i < S_; i += 256) row[i] = 0.f;   // so PV can read full tiles
}

// ---------------- O = P @ V (causal k-tiles only) ----------------------------
__global__ void __launch_bounds__(256) pv_kernel(
    const float* __restrict__ scores, const float* __restrict__ qkv,
    float* __restrict__ attn)
{
    int qt = blockIdx.x;
    int bh = blockIdx.z;
    int b = bh / H_, h = bh - b * H_;

    __shared__ float Ps[16][68];
    __shared__ float Vs[16][64];

    int tid = threadIdx.x;
    const float* P  = scores + (size_t)bh * S_ * S_ + (size_t)(qt * 64) * S_;
    const float* Vb = qkv + (size_t)b * S_ * (3 * D_) + 2 * D_ + h * HD_;

    int warp = tid >> 5, lane = tid & 31;
    int qi = ((warp >> 1) << 4) + ((lane >> 3) << 2);
    int di = ((warp & 1) << 5) + ((lane & 7) << 2);

    int pq = tid >> 2, pk4 = (tid & 3) << 2;     // P tile 64x16
    int vk = tid >> 4, vd4 = (tid & 15) << 2;    // V tile 16x64

    float acc[4][4] = {};
    int nk = (qt + 1) * 64;                      // causal frontier
    for (int k0 = 0; k0 < nk; k0 += 16) {
        float4 pv = *(const float4*)(P + (size_t)pq * S_ + k0 + pk4);
        Ps[pk4 + 0][pq] = pv.x; Ps[pk4 + 1][pq] = pv.y;
        Ps[pk4 + 2][pq] = pv.z; Ps[pk4 + 3][pq] = pv.w;
        *(float4*)&Vs[vk][vd4] = *(const float4*)(Vb + (size_t)(k0 + vk) * (3 * D_) + vd4);
        __syncthreads();
        #pragma unroll
        for (int kk = 0; kk < 16; kk++) {
            float4 pa = *(const float4*)&Ps[kk][qi];
            float4 vv = *(const float4*)&Vs[kk][di];
            float a[4] = {pa.x, pa.y, pa.z, pa.w};
            float c[4] = {vv.x, vv.y, vv.z, vv.w};
            #pragma unroll
            for (int i = 0; i < 4; i++)
                #pragma unroll
                for (int j = 0; j < 4; j++)
                    acc[i][j] = fmaf(a[i], c[j], acc[i][j]);
        }
        __syncthreads();
    }

    float* o = attn + ((size_t)(b * S_ + qt * 64 + qi)) * D_ + h * HD_ + di;
    #pragma unroll
    for (int i = 0; i < 4; i++)
        *(float4*)(o + (size_t)i * D_) =
            make_float4(acc[i][0], acc[i][1], acc[i][2], acc[i][3]);
}

// ---------------- host orchestration -----------------------------------------
extern "C" void kernel_launch(void* const* d_in, const int* in_sizes, int n_in,
                              void* d_out, int out_size)
{
    const int*   ids  = (const int*)d_in[0];
    const float* tok  = (const float*)d_in[1];
    const float* pos  = (const float*)d_in[2];
    const float* ln1g = (const float*)d_in[3];
    const float* ln1b = (const float*)d_in[4];
    const float* qkvw = (const float*)d_in[5];
    const float* qkvb = (const float*)d_in[6];
    const float* outw = (const float*)d_in[7];
    const float* outb = (const float*)d_in[8];
    const float* ln2g = (const float*)d_in[9];
    const float* ln2b = (const float*)d_in[10];
    const float* f1w  = (const float*)d_in[11];
    const float* f1b  = (const float*)d_in[12];
    const float* f2w  = (const float*)d_in[13];
    const float* f2b  = (const float*)d_in[14];
    const float* lnfg = (const float*)d_in[15];
    const float* lnfb = (const float*)d_in[16];
    float* logits = (float*)d_out;

    float *x, *h, *qkv, *attn, *ff, *scores;
    cudaGetSymbolAddress((void**)&x,      g_x);
    cudaGetSymbolAddress((void**)&h,      g_h);
    cudaGetSymbolAddress((void**)&qkv,    g_qkv);
    cudaGetSymbolAddress((void**)&attn,   g_attn);
    cudaGetSymbolAddress((void**)&ff,     g_ff);
    cudaGetSymbolAddress((void**)&scores, g_scores);

    embed_kernel<<<(T_ * D_) / 256, 256>>>(ids, tok, pos, x);

    for (int l = 0; l < L_; l++) {
        ln_kernel<<<T_, 256>>>(x, ln1g + l * D_, ln1b + l * D_, h);

        gemm_nn<0><<<dim3((3 * D_) / 128, T_ / 128), 256>>>(
            h, qkvw + (size_t)l * D_ * 3 * D_, qkvb + (size_t)l * 3 * D_,
            nullptr, qkv, T_, 3 * D_, D_);

        scores_kernel<<<dim3(16, 16, B_ * H_), 256>>>(qkv, scores);
        softmax_kernel<<<B_ * H_ * S_, 256>>>(scores);
        pv_kernel<<<dim3(16, 1, B_ * H_), 256>>>(scores, qkv, attn);

        gemm_nn<1><<<dim3(D_ / 128, T_ / 128), 256>>>(
            attn, outw + (size_t)l * D_ * D_, outb + (size_t)l * D_,
            x, x, T_, D_, D_);

        ln_kernel<<<T_, 256>>>(x, ln2g + l * D_, ln2b + l * D_, h);

        gemm_nn<2><<<dim3(F_ / 128, T_ / 128), 256>>>(
            h, f1w + (size_t)l * D_ * F_, f1b + (size_t)l * F_,
            nullptr, ff, T_, F_, D_);

        gemm_nn<1><<<dim3(D_ / 128, T_ / 128), 256>>>(
            ff, f2w + (size_t)l * F_ * D_, f2b + (size_t)l * D_,
            x, x, T_, D_, F_);
    }

    ln_kernel<<<T_, 256>>>(x, lnfg, lnfb, h);
    gemm_nt<<<dim3((V_ + 127) / 128, T_ / 128), 256>>>(h, tok, logits, T_, V_, D_);
}